// round 12
// baseline (speedup 1.0000x reference)
#include <cuda_runtime.h>
#include <cuda_fp16.h>
#include <math.h>
#include <stdint.h>

#define B_ 1024
#define D_ 512
#define C_ 100000
#define C_PAD 100096        // 782 * 128
#define SCALE_ 30.0f
#define MARGIN_ 0.4f

#define BM 128
#define BN 128
#define BK 32
#define NT (D_ / BK)        // 16 k-tiles
#define STAGES 5
#define NYTILES (C_PAD / BN)   // 782

#define STRB 80             // 32 fp16 = 64B data, pad to 80B (conflict-free ldmatrix)
#define OFF_A 0
#define OFF_B (128 * STRB)
#define STG_BYTES (2 * 128 * STRB)      // 20480 per stage
#define SMEM_TOTAL (STAGES * STG_BYTES) // 102400

// ---------------- device scratch ----------------
__device__ __half g_Wh[(size_t)C_PAD * D_];   // normalized W fp16 (padding rows stay 0)
__device__ __half g_Ah[B_ * D_];              // normalized x fp16
__device__ float g_rowsum[B_];
__device__ int   g_wflag[NYTILES];            // per-N-tile conversion-done flag

// ---------------- helpers ----------------
__device__ __forceinline__ uint32_t smem_u32(const void* p) {
    uint32_t a;
    asm("{ .reg .u64 t; cvta.to.shared.u64 t, %1; cvt.u32.u64 %0, t; }" : "=r"(a) : "l"(p));
    return a;
}
__device__ __forceinline__ void cp16(uint32_t dst, const void* src) {
    asm volatile("cp.async.cg.shared.global [%0], [%1], 16;" :: "r"(dst), "l"(src));
}
#define CP_COMMIT() asm volatile("cp.async.commit_group;" ::: "memory")
#define CP_WAIT(n)  asm volatile("cp.async.wait_group %0;" :: "n"(n) : "memory")

#define LDSM4(r, addr) \
    asm volatile("ldmatrix.sync.aligned.m8n8.x4.shared.b16 {%0,%1,%2,%3}, [%4];" \
        : "=r"((r)[0]), "=r"((r)[1]), "=r"((r)[2]), "=r"((r)[3]) : "r"(addr))

#define MMA16816F16(c, a, b) \
    asm volatile("mma.sync.aligned.m16n8k16.row.col.f32.f16.f16.f32 " \
        "{%0,%1,%2,%3}, {%4,%5,%6,%7}, {%8,%9}, {%0,%1,%2,%3};" \
        : "+f"((c)[0]), "+f"((c)[1]), "+f"((c)[2]), "+f"((c)[3]) \
        : "r"((a)[0]), "r"((a)[1]), "r"((a)[2]), "r"((a)[3]), "r"((b)[0]), "r"((b)[1]))

// ---------------------------------------------------------------------------
// Kernel 1: normalize x -> fp16 (warp per row); zero rowsum + wflags.
// ---------------------------------------------------------------------------
__global__ void split_kernel(const float* __restrict__ x) {
    int g = blockIdx.x * blockDim.x + threadIdx.x;
    if (g < B_) g_rowsum[g] = 0.0f;
    if (g < NYTILES) g_wflag[g] = 0;

    int row = g >> 5, lane = g & 31;
    if (row >= B_) return;

    const float* src = x + (size_t)row * D_;
    __half* dst = g_Ah + (size_t)row * D_;

    const float4* s4 = (const float4*)src;
    float4 v[4];
    float s = 0.0f;
#pragma unroll
    for (int i = 0; i < 4; i++) {
        v[i] = s4[lane + i * 32];
        s += v[i].x * v[i].x + v[i].y * v[i].y + v[i].z * v[i].z + v[i].w * v[i].w;
    }
#pragma unroll
    for (int o = 16; o > 0; o >>= 1) s += __shfl_xor_sync(0xffffffffu, s, o);
    float inv = 1.0f / fmaxf(sqrtf(s), 1e-12f);

#pragma unroll
    for (int i = 0; i < 4; i++) {
        int idx = (lane + i * 32) * 4;
        *(__half2*)(dst + idx)     = __floats2half2_rn(v[i].x * inv, v[i].y * inv);
        *(__half2*)(dst + idx + 2) = __floats2half2_rn(v[i].z * inv, v[i].w * inv);
    }
}

// ---------------------------------------------------------------------------
// Kernel 2: fp16 HMMA GEMM with FUSED W conversion.
// blockIdx.x==0 CTA of each N-tile normalizes its 128 W rows -> g_Wh (L2),
// flags completion; siblings (x=1..7) spin. Deadlock-free: converter bid
// (y*8) always dispatches before spinner bids (y*8+1..7).
// CTA 128x128, 4 warps (2x2), warp tile 64x64, 5-stage cp.async,
// one barrier per k-tile, occupancy 2, streaming cosine stores + exp-rowsum.
// ---------------------------------------------------------------------------
__device__ __forceinline__ void load_tile(uint32_t sb, int stage, int rowBase,
                                          int colBase, int kt, int tid) {
    uint32_t base = sb + stage * STG_BYTES;
    int k0 = kt * BK;
#pragma unroll
    for (int h = 0; h < 4; h++) {
        int idx = tid + h * 128;          // 0..511
        int r = idx >> 2, seg = idx & 3;  // row 0..127, 16B segment 0..3
        uint32_t d = (uint32_t)(r * STRB + seg * 16);
        cp16(base + OFF_A + d, g_Ah + (size_t)(rowBase + r) * D_ + k0 + seg * 8);
        cp16(base + OFF_B + d, g_Wh + (size_t)(colBase + r) * D_ + k0 + seg * 8);
    }
}

// Normalize one W row (fp32 -> fp16), warp-collective.
__device__ __forceinline__ void convert_row(const float* __restrict__ w,
                                            int row, int lane) {
    const float4* s4 = (const float4*)(w + (size_t)row * D_);
    __half* dst = g_Wh + (size_t)row * D_;
    float4 v[4];
    float s = 0.0f;
#pragma unroll
    for (int i = 0; i < 4; i++) {
        v[i] = s4[lane + i * 32];
        s += v[i].x * v[i].x + v[i].y * v[i].y + v[i].z * v[i].z + v[i].w * v[i].w;
    }
#pragma unroll
    for (int o = 16; o > 0; o >>= 1) s += __shfl_xor_sync(0xffffffffu, s, o);
    float inv = 1.0f / fmaxf(sqrtf(s), 1e-12f);
#pragma unroll
    for (int i = 0; i < 4; i++) {
        int idx = (lane + i * 32) * 4;
        *(__half2*)(dst + idx)     = __floats2half2_rn(v[i].x * inv, v[i].y * inv);
        *(__half2*)(dst + idx + 2) = __floats2half2_rn(v[i].z * inv, v[i].w * inv);
    }
}

__global__ __launch_bounds__(128, 2) void gemm_mma(const float* __restrict__ w,
                                                   float* __restrict__ cosOut) {
    extern __shared__ __align__(128) char smem[];
    uint32_t sb = smem_u32(smem);
    const int tid = threadIdx.x;
    const int lane = tid & 31, wid = tid >> 5;
    const int warpM = wid & 1;        // 2 warps in M (64 rows each)
    const int warpN = wid >> 1;       // 2 warps in N (64 cols each)
    const int rowBase = blockIdx.x * BM;   // 8 M tiles (fast dim)
    const int colBase = blockIdx.y * BN;   // 782 N tiles

    // ---- fused W conversion / wait ----
    if (blockIdx.x == 0) {
        const int rowsHere = min(BN, C_ - colBase);   // 128, or 32 for last tile
        // two rows per warp in flight for MLP
        for (int r0 = wid * 2; r0 < rowsHere; r0 += 8) {
            convert_row(w, colBase + r0, lane);
            if (r0 + 1 < rowsHere) convert_row(w, colBase + r0 + 1, lane);
        }
        __threadfence();
        __syncthreads();
        if (tid == 0) atomicExch(&g_wflag[blockIdx.y], 1);
    } else {
        if (tid == 0) {
            while (atomicAdd(&g_wflag[blockIdx.y], 0) == 0) __nanosleep(200);
        }
        __syncthreads();
    }

    float acc[4][8][4];
#pragma unroll
    for (int i = 0; i < 4; i++)
#pragma unroll
        for (int j = 0; j < 8; j++)
#pragma unroll
            for (int k = 0; k < 4; k++) acc[i][j][k] = 0.0f;

    // prologue: fill pipeline (STAGES-1 = 4 groups in flight)
#pragma unroll
    for (int s = 0; s < STAGES - 1; s++) {
        load_tile(sb, s, rowBase, colBase, s, tid);
        CP_COMMIT();
    }

    // ldmatrix lane offsets (proven mappings from R5/R7/R9/R10)
    const uint32_t aLaneOff = (uint32_t)((lane & 15) * STRB + (lane >> 4) * 16);
    const uint32_t bLaneOff = (uint32_t)((lane & 7) * STRB + ((lane >> 3) & 1) * 16 +
                                         (lane >> 4) * 8 * STRB);

#pragma unroll
    for (int kt = 0; kt < NT; kt++) {
        // RAW: my own cp.async groups for stage kt%5 done (<=3 newer groups)
        CP_WAIT(STAGES - 2);
        // WAR + cross-thread RAW: all warps past compute kt-1 (which read stage
        // (kt+4)%5, the one written below); all waits drained before barrier.
        __syncthreads();
        if (kt + STAGES - 1 < NT)
            load_tile(sb, (kt + STAGES - 1) % STAGES, rowBase, colBase,
                      kt + STAGES - 1, tid);
        CP_COMMIT();   // UNCONDITIONAL: empty tail groups keep wait_group's
                       // count invariant (R6 lesson).
        uint32_t st = sb + (kt % STAGES) * STG_BYTES;

#pragma unroll
        for (int ks = 0; ks < 2; ks++) {
            uint32_t kOff = ks * 32;   // 16 fp16 = 32 B
            uint32_t a[4][4], b[8][2];
#pragma unroll
            for (int nb = 0; nb < 4; nb++) {   // B first: shared across all mi
                uint32_t t[4];
                LDSM4(t, st + OFF_B +
                    (uint32_t)((warpN * 64 + nb * 16) * STRB) + kOff + bLaneOff);
                b[nb * 2][0] = t[0]; b[nb * 2][1] = t[1];
                b[nb * 2 + 1][0] = t[2]; b[nb * 2 + 1][1] = t[3];
            }
#pragma unroll
            for (int mi = 0; mi < 4; mi++)
                LDSM4(a[mi], st + OFF_A +
                    (uint32_t)((warpM * 64 + mi * 16) * STRB) + kOff + aLaneOff);
#pragma unroll
            for (int mi = 0; mi < 4; mi++)
#pragma unroll
                for (int ni = 0; ni < 8; ni++)
                    MMA16816F16(acc[mi][ni], a[mi], b[ni]);
        }
        // no trailing barrier: stage reuse distance = STAGES-1 iterations
    }

    // ---------------- epilogue ----------------
    __syncthreads();   // all MMA reads done before smem reuse for srow
    float* srow = (float*)smem;
    if (tid < BM) srow[tid] = 0.0f;
    __syncthreads();

    const int g = lane >> 2;
    const int qc = (lane & 3) * 2;
#pragma unroll
    for (int mi = 0; mi < 4; mi++) {
        float p0 = 0.0f, p1 = 0.0f;
        const int rloc = warpM * 64 + mi * 16 + g;
        const int r0 = rowBase + rloc;
#pragma unroll
        for (int ni = 0; ni < 8; ni++) {
            int col = colBase + warpN * 64 + ni * 8 + qc;
            if (col < C_) {   // col even, C_ even -> covers col+1 too
                float c0 = acc[mi][ni][0], c1 = acc[mi][ni][1];
                float c2 = acc[mi][ni][2], c3 = acc[mi][ni][3];
                // streaming scalar stores (cosOut = out+1 is only 4B-aligned)
                __stcs(&cosOut[(size_t)r0 * C_ + col],           c0);
                __stcs(&cosOut[(size_t)r0 * C_ + col + 1],       c1);
                __stcs(&cosOut[(size_t)(r0 + 8) * C_ + col],     c2);
                __stcs(&cosOut[(size_t)(r0 + 8) * C_ + col + 1], c3);
                p0 += __expf(SCALE_ * c0) + __expf(SCALE_ * c1);
                p1 += __expf(SCALE_ * c2) + __expf(SCALE_ * c3);
            }
        }
        atomicAdd(&srow[rloc], p0);
        atomicAdd(&srow[rloc + 8], p1);
    }
    __syncthreads();
    if (tid < BM)
        atomicAdd(&g_rowsum[rowBase + tid], srow[tid]);
}

// ---------------------------------------------------------------------------
// Kernel 3: per-sample CosFace loss + mean. label is int32.
// ---------------------------------------------------------------------------
__global__ void loss_kernel(const float* __restrict__ cosOut,
                            const int* __restrict__ label,
                            float* __restrict__ out) {
    __shared__ float red[B_];
    const int b = threadIdx.x;
    int lab = max(0, min(label[b], C_ - 1));
    float tgt = cosOut[(size_t)b * C_ + (size_t)lab];
    float numerator = SCALE_ * (tgt - MARGIN_);
    float excl = g_rowsum[b] - __expf(SCALE_ * tgt);
    float denom = expf(numerator) + excl;
    float loss = numerator - logf(denom);
    red[b] = loss;
    __syncthreads();
#pragma unroll
    for (int o = B_ / 2; o > 0; o >>= 1) {
        if (b < o) red[b] += red[b + o];
        __syncthreads();
    }
    if (b == 0) out[0] = -red[0] / (float)B_;
}

// ---------------------------------------------------------------------------
extern "C" void kernel_launch(void* const* d_in, const int* in_sizes, int n_in,
                              void* d_out, int out_size) {
    const float* x     = (const float*)d_in[0];
    const int*   label = (const int*)d_in[1];
    const float* w     = (const float*)d_in[2];

    float* out = (float*)d_out;
    bool has_loss = (out_size > B_ * C_);
    float* cosOut = has_loss ? (out + 1) : out;

    // 1) normalize x -> fp16; zero rowsum + wflags (A only: 1024 warps)
    split_kernel<<<(B_ * 32) / 256, 256>>>(x);

    // 2) fp16 HMMA GEMM with fused W conversion + fused epilogue
    {
        static int smem_set = 0;
        if (!smem_set) {
            cudaFuncSetAttribute(gemm_mma, cudaFuncAttributeMaxDynamicSharedMemorySize,
                                 SMEM_TOTAL);
            smem_set = 1;
        }
        dim3 grid(B_ / BM, NYTILES);   // (8, 782): x==0 CTA converts its W tile
        gemm_mma<<<grid, 128, SMEM_TOTAL>>>(w, cosOut);
    }
    // 3) loss
    if (has_loss)
        loss_kernel<<<1, B_>>>(cosOut, label, out);
}

// round 13
// speedup vs baseline: 1.9932x; 1.9932x over previous
#include <cuda_runtime.h>
#include <cuda_fp16.h>
#include <math.h>
#include <stdint.h>

#define B_ 1024
#define D_ 512
#define C_ 100000
#define C_PAD 100096        // 782 * 128
#define SCALE_ 30.0f
#define MARGIN_ 0.4f

#define BM 128
#define BN 128
#define BK 32
#define NT (D_ / BK)        // 16 k-tiles
#define STAGES 5

#define STRB 80             // 32 fp16 = 64B data, pad to 80B (conflict-free ldmatrix)
#define OFF_A 0
#define OFF_B (128 * STRB)
#define STG_BYTES (2 * 128 * STRB)      // 20480 per stage
#define SMEM_TOTAL (STAGES * STG_BYTES) // 102400

// ---------------- device scratch ----------------
__device__ __half g_Wh[(size_t)C_PAD * D_];   // normalized W, fp16 (padding rows stay 0)
__device__ __half g_Ah[B_ * D_];              // normalized x, fp16
__device__ float g_rowsum[B_];

// ---------------- helpers ----------------
__device__ __forceinline__ uint32_t smem_u32(const void* p) {
    uint32_t a;
    asm("{ .reg .u64 t; cvta.to.shared.u64 t, %1; cvt.u32.u64 %0, t; }" : "=r"(a) : "l"(p));
    return a;
}
__device__ __forceinline__ void cp16(uint32_t dst, const void* src) {
    asm volatile("cp.async.cg.shared.global [%0], [%1], 16;" :: "r"(dst), "l"(src));
}
#define CP_COMMIT() asm volatile("cp.async.commit_group;" ::: "memory")
#define CP_WAIT(n)  asm volatile("cp.async.wait_group %0;" :: "n"(n) : "memory")

#define LDSM4(r, addr) \
    asm volatile("ldmatrix.sync.aligned.m8n8.x4.shared.b16 {%0,%1,%2,%3}, [%4];" \
        : "=r"((r)[0]), "=r"((r)[1]), "=r"((r)[2]), "=r"((r)[3]) : "r"(addr))

#define MMA16816F16(c, a, b) \
    asm volatile("mma.sync.aligned.m16n8k16.row.col.f32.f16.f16.f32 " \
        "{%0,%1,%2,%3}, {%4,%5,%6,%7}, {%8,%9}, {%0,%1,%2,%3};" \
        : "+f"((c)[0]), "+f"((c)[1]), "+f"((c)[2]), "+f"((c)[3]) \
        : "r"((a)[0]), "r"((a)[1]), "r"((a)[2]), "r"((a)[3]), "r"((b)[0]), "r"((b)[1]))

// ---------------------------------------------------------------------------
// Kernel 1: fused normalize -> fp16. One warp per row. Zeroes g_rowsum.
// Source reads use __ldcs (touch-once) so the g_Wh writes stay in L2 for the
// GEMM that launches immediately after.
// ---------------------------------------------------------------------------
__global__ void split_kernel(const float* __restrict__ x, const float* __restrict__ w) {
    int g = blockIdx.x * blockDim.x + threadIdx.x;
    if (g < B_) g_rowsum[g] = 0.0f;

    int row = g >> 5, lane = g & 31;
    if (row >= C_ + B_) return;

    const float* src;
    __half* dst;
    if (row < C_) {
        src = w + (size_t)row * D_;
        dst = g_Wh + (size_t)row * D_;
    } else {
        int r = row - C_;
        src = x + (size_t)r * D_;
        dst = g_Ah + (size_t)r * D_;
    }

    const float4* s4 = (const float4*)src;
    float4 v[4];
    float s = 0.0f;
#pragma unroll
    for (int i = 0; i < 4; i++) {
        v[i] = __ldcs(&s4[lane + i * 32]);   // evict-first: sources are touch-once
        s += v[i].x * v[i].x + v[i].y * v[i].y + v[i].z * v[i].z + v[i].w * v[i].w;
    }
#pragma unroll
    for (int o = 16; o > 0; o >>= 1) s += __shfl_xor_sync(0xffffffffu, s, o);
    float inv = 1.0f / fmaxf(sqrtf(s), 1e-12f);

#pragma unroll
    for (int i = 0; i < 4; i++) {
        int idx = (lane + i * 32) * 4;
        *(__half2*)(dst + idx)     = __floats2half2_rn(v[i].x * inv, v[i].y * inv);
        *(__half2*)(dst + idx + 2) = __floats2half2_rn(v[i].z * inv, v[i].w * inv);
    }
}

// ---------------------------------------------------------------------------
// Kernel 2: fp16 HMMA GEMM. CTA 128x128, 4 warps (2x2), warp tile 64x64,
// 5-stage cp.async, ONE barrier per k-tile, occupancy 2.
// Fused cosine store (streaming) + exp-rowsum epilogue.  (R10 proven config)
// ---------------------------------------------------------------------------
__device__ __forceinline__ void load_tile(uint32_t sb, int stage, int rowBase,
                                          int colBase, int kt, int tid) {
    uint32_t base = sb + stage * STG_BYTES;
    int k0 = kt * BK;
#pragma unroll
    for (int h = 0; h < 4; h++) {
        int idx = tid + h * 128;          // 0..511
        int r = idx >> 2, seg = idx & 3;  // row 0..127, 16B segment 0..3
        uint32_t d = (uint32_t)(r * STRB + seg * 16);
        cp16(base + OFF_A + d, g_Ah + (size_t)(rowBase + r) * D_ + k0 + seg * 8);
        cp16(base + OFF_B + d, g_Wh + (size_t)(colBase + r) * D_ + k0 + seg * 8);
    }
}

__global__ __launch_bounds__(128, 2) void gemm_mma(float* __restrict__ cosOut) {
    extern __shared__ __align__(128) char smem[];
    uint32_t sb = smem_u32(smem);
    const int tid = threadIdx.x;
    const int lane = tid & 31, wid = tid >> 5;
    const int warpM = wid & 1;        // 2 warps in M (64 rows each)
    const int warpN = wid >> 1;       // 2 warps in N (64 cols each)
    const int rowBase = blockIdx.x * BM;   // 8 M tiles (fast dim -> W reuse per wave)
    const int colBase = blockIdx.y * BN;   // 782 N tiles

    float acc[4][8][4];
#pragma unroll
    for (int i = 0; i < 4; i++)
#pragma unroll
        for (int j = 0; j < 8; j++)
#pragma unroll
            for (int k = 0; k < 4; k++) acc[i][j][k] = 0.0f;

    // prologue: fill pipeline (STAGES-1 = 4 groups in flight)
#pragma unroll
    for (int s = 0; s < STAGES - 1; s++) {
        load_tile(sb, s, rowBase, colBase, s, tid);
        CP_COMMIT();
    }

    // ldmatrix lane offsets (proven mappings from R5/R7/R9/R10)
    const uint32_t aLaneOff = (uint32_t)((lane & 15) * STRB + (lane >> 4) * 16);
    const uint32_t bLaneOff = (uint32_t)((lane & 7) * STRB + ((lane >> 3) & 1) * 16 +
                                         (lane >> 4) * 8 * STRB);

#pragma unroll
    for (int kt = 0; kt < NT; kt++) {
        // RAW: my own cp.async groups for stage kt%5 done (<=3 newer groups)
        CP_WAIT(STAGES - 2);
        // WAR + cross-thread RAW: all warps past compute kt-1 (which read stage
        // (kt+4)%5, the one written below); all waits drained before barrier.
        __syncthreads();
        if (kt + STAGES - 1 < NT)
            load_tile(sb, (kt + STAGES - 1) % STAGES, rowBase, colBase,
                      kt + STAGES - 1, tid);
        CP_COMMIT();   // UNCONDITIONAL: empty tail groups keep wait_group's
                       // count invariant (R6 lesson).
        uint32_t st = sb + (kt % STAGES) * STG_BYTES;

#pragma unroll
        for (int ks = 0; ks < 2; ks++) {
            uint32_t kOff = ks * 32;   // 16 fp16 = 32 B
            uint32_t a[4][4], b[8][2];
#pragma unroll
            for (int nb = 0; nb < 4; nb++) {   // B first: shared across all mi
                uint32_t t[4];
                LDSM4(t, st + OFF_B +
                    (uint32_t)((warpN * 64 + nb * 16) * STRB) + kOff + bLaneOff);
                b[nb * 2][0] = t[0]; b[nb * 2][1] = t[1];
                b[nb * 2 + 1][0] = t[2]; b[nb * 2 + 1][1] = t[3];
            }
#pragma unroll
            for (int mi = 0; mi < 4; mi++)
                LDSM4(a[mi], st + OFF_A +
                    (uint32_t)((warpM * 64 + mi * 16) * STRB) + kOff + aLaneOff);
#pragma unroll
            for (int mi = 0; mi < 4; mi++)
#pragma unroll
                for (int ni = 0; ni < 8; ni++)
                    MMA16816F16(acc[mi][ni], a[mi], b[ni]);
        }
        // no trailing barrier: stage reuse distance = STAGES-1 iterations
    }

    // ---------------- epilogue ----------------
    __syncthreads();   // all MMA reads done before smem reuse for srow
    float* srow = (float*)smem;
    if (tid < BM) srow[tid] = 0.0f;
    __syncthreads();

    const int g = lane >> 2;
    const int qc = (lane & 3) * 2;
#pragma unroll
    for (int mi = 0; mi < 4; mi++) {
        float p0 = 0.0f, p1 = 0.0f;
        const int rloc = warpM * 64 + mi * 16 + g;
        const int r0 = rowBase + rloc;
#pragma unroll
        for (int ni = 0; ni < 8; ni++) {
            int col = colBase + warpN * 64 + ni * 8 + qc;
            if (col < C_) {   // col even, C_ even -> covers col+1 too
                float c0 = acc[mi][ni][0], c1 = acc[mi][ni][1];
                float c2 = acc[mi][ni][2], c3 = acc[mi][ni][3];
                // streaming scalar stores (cosOut = out+1 is only 4B-aligned;
                // .cs keeps the 410MB write-once stream out of L2's way)
                __stcs(&cosOut[(size_t)r0 * C_ + col],           c0);
                __stcs(&cosOut[(size_t)r0 * C_ + col + 1],       c1);
                __stcs(&cosOut[(size_t)(r0 + 8) * C_ + col],     c2);
                __stcs(&cosOut[(size_t)(r0 + 8) * C_ + col + 1], c3);
                p0 += __expf(SCALE_ * c0) + __expf(SCALE_ * c1);
                p1 += __expf(SCALE_ * c2) + __expf(SCALE_ * c3);
            }
        }
        atomicAdd(&srow[rloc], p0);
        atomicAdd(&srow[rloc + 8], p1);
    }
    __syncthreads();
    if (tid < BM)
        atomicAdd(&g_rowsum[rowBase + tid], srow[tid]);
}

// ---------------------------------------------------------------------------
// Kernel 3: per-sample CosFace loss + mean. label is int32.
// ---------------------------------------------------------------------------
__global__ void loss_kernel(const float* __restrict__ cosOut,
                            const int* __restrict__ label,
                            float* __restrict__ out) {
    __shared__ float red[B_];
    const int b = threadIdx.x;
    int lab = max(0, min(label[b], C_ - 1));
    float tgt = cosOut[(size_t)b * C_ + (size_t)lab];
    float numerator = SCALE_ * (tgt - MARGIN_);
    float excl = g_rowsum[b] - __expf(SCALE_ * tgt);
    float denom = expf(numerator) + excl;
    float loss = numerator - logf(denom);
    red[b] = loss;
    __syncthreads();
#pragma unroll
    for (int o = B_ / 2; o > 0; o >>= 1) {
        if (b < o) red[b] += red[b + o];
        __syncthreads();
    }
    if (b == 0) out[0] = -red[0] / (float)B_;
}

// ---------------------------------------------------------------------------
extern "C" void kernel_launch(void* const* d_in, const int* in_sizes, int n_in,
                              void* d_out, int out_size) {
    const float* x     = (const float*)d_in[0];
    const int*   label = (const int*)d_in[1];
    const float* w     = (const float*)d_in[2];

    float* out = (float*)d_out;
    bool has_loss = (out_size > B_ * C_);
    float* cosOut = has_loss ? (out + 1) : out;

    // 1) normalize -> fp16 (x + W, one warp per row)
    {
        const int rows = C_ + B_;
        const int blocks = (rows * 32 + 255) / 256;
        split_kernel<<<blocks, 256>>>(x, w);
    }
    // 2) fp16 HMMA GEMM + fused epilogue
    {
        static int smem_set = 0;
        if (!smem_set) {
            cudaFuncSetAttribute(gemm_mma, cudaFuncAttributeMaxDynamicSharedMemorySize,
                                 SMEM_TOTAL);
            smem_set = 1;
        }
        dim3 grid(B_ / BM, C_PAD / BN);   // (8, 782): M fast -> W tile reuse per wave
        gemm_mma<<<grid, 128, SMEM_TOTAL>>>(cosOut);
    }
    // 3) loss
    if (has_loss)
        loss_kernel<<<1, B_>>>(cosOut, label, out);
}

// round 14
// speedup vs baseline: 2.0279x; 1.0174x over previous
#include <cuda_runtime.h>
#include <cuda_fp16.h>
#include <math.h>
#include <stdint.h>

#define B_ 1024
#define D_ 512
#define C_ 100000
#define C_PAD 100096        // 782 * 128
#define SCALE_ 30.0f
#define MARGIN_ 0.4f

#define BM 128
#define BN 128
#define BK 64
#define NT (D_ / BK)        // 8 k-tiles
#define STAGES 3

#define STRB 144            // 64 fp16 = 128B data + 16B pad (conflict-free ldmatrix)
#define OFF_A 0
#define OFF_B (128 * STRB)
#define STG_BYTES (2 * 128 * STRB)      // 36864 per stage
#define SMEM_TOTAL (STAGES * STG_BYTES) // 110592

// ---------------- device scratch ----------------
__device__ __half g_Wh[(size_t)C_PAD * D_];   // normalized W, fp16 (padding rows stay 0)
__device__ __half g_Ah[B_ * D_];              // normalized x, fp16
__device__ float g_rowsum[B_];

// ---------------- helpers ----------------
__device__ __forceinline__ uint32_t smem_u32(const void* p) {
    uint32_t a;
    asm("{ .reg .u64 t; cvta.to.shared.u64 t, %1; cvt.u32.u64 %0, t; }" : "=r"(a) : "l"(p));
    return a;
}
__device__ __forceinline__ void cp16(uint32_t dst, const void* src) {
    asm volatile("cp.async.cg.shared.global [%0], [%1], 16;" :: "r"(dst), "l"(src));
}
#define CP_COMMIT() asm volatile("cp.async.commit_group;" ::: "memory")
#define CP_WAIT(n)  asm volatile("cp.async.wait_group %0;" :: "n"(n) : "memory")

#define LDSM4(r, addr) \
    asm volatile("ldmatrix.sync.aligned.m8n8.x4.shared.b16 {%0,%1,%2,%3}, [%4];" \
        : "=r"((r)[0]), "=r"((r)[1]), "=r"((r)[2]), "=r"((r)[3]) : "r"(addr))

#define MMA16816F16(c, a, b) \
    asm volatile("mma.sync.aligned.m16n8k16.row.col.f32.f16.f16.f32 " \
        "{%0,%1,%2,%3}, {%4,%5,%6,%7}, {%8,%9}, {%0,%1,%2,%3};" \
        : "+f"((c)[0]), "+f"((c)[1]), "+f"((c)[2]), "+f"((c)[3]) \
        : "r"((a)[0]), "r"((a)[1]), "r"((a)[2]), "r"((a)[3]), "r"((b)[0]), "r"((b)[1]))

// ---------------------------------------------------------------------------
// Kernel 1: fused normalize -> fp16. One warp per row. Zeroes g_rowsum.
// ---------------------------------------------------------------------------
__global__ void split_kernel(const float* __restrict__ x, const float* __restrict__ w) {
    int g = blockIdx.x * blockDim.x + threadIdx.x;
    if (g < B_) g_rowsum[g] = 0.0f;

    int row = g >> 5, lane = g & 31;
    if (row >= C_ + B_) return;

    const float* src;
    __half* dst;
    if (row < C_) {
        src = w + (size_t)row * D_;
        dst = g_Wh + (size_t)row * D_;
    } else {
        int r = row - C_;
        src = x + (size_t)r * D_;
        dst = g_Ah + (size_t)r * D_;
    }

    const float4* s4 = (const float4*)src;
    float4 v[4];
    float s = 0.0f;
#pragma unroll
    for (int i = 0; i < 4; i++) {
        v[i] = s4[lane + i * 32];
        s += v[i].x * v[i].x + v[i].y * v[i].y + v[i].z * v[i].z + v[i].w * v[i].w;
    }
#pragma unroll
    for (int o = 16; o > 0; o >>= 1) s += __shfl_xor_sync(0xffffffffu, s, o);
    float inv = 1.0f / fmaxf(sqrtf(s), 1e-12f);

#pragma unroll
    for (int i = 0; i < 4; i++) {
        int idx = (lane + i * 32) * 4;
        *(__half2*)(dst + idx)     = __floats2half2_rn(v[i].x * inv, v[i].y * inv);
        *(__half2*)(dst + idx + 2) = __floats2half2_rn(v[i].z * inv, v[i].w * inv);
    }
}

// ---------------------------------------------------------------------------
// Kernel 2: fp16 HMMA GEMM. CTA 128x128, 4 warps (2x2), warp tile 64x64,
// BK=64 (8 k-tiles -> HALF the barriers/waits/commits of BK=32),
// 3-stage cp.async, ONE barrier per k-tile, occupancy 2.
// Fused cosine store (streaming) + exp-rowsum epilogue.
// ---------------------------------------------------------------------------
__device__ __forceinline__ void load_tile(uint32_t sb, int stage, int rowBase,
                                          int colBase, int kt, int tid) {
    uint32_t base = sb + stage * STG_BYTES;
    int k0 = kt * BK;
#pragma unroll
    for (int h = 0; h < 8; h++) {
        int idx = tid + h * 128;          // 0..1023
        int r = idx >> 3, seg = idx & 7;  // row 0..127, 16B segment 0..7
        uint32_t d = (uint32_t)(r * STRB + seg * 16);
        cp16(base + OFF_A + d, g_Ah + (size_t)(rowBase + r) * D_ + k0 + seg * 8);
        cp16(base + OFF_B + d, g_Wh + (size_t)(colBase + r) * D_ + k0 + seg * 8);
    }
}

__global__ __launch_bounds__(128, 2) void gemm_mma(float* __restrict__ cosOut) {
    extern __shared__ __align__(128) char smem[];
    uint32_t sb = smem_u32(smem);
    const int tid = threadIdx.x;
    const int lane = tid & 31, wid = tid >> 5;
    const int warpM = wid & 1;        // 2 warps in M (64 rows each)
    const int warpN = wid >> 1;       // 2 warps in N (64 cols each)
    const int rowBase = blockIdx.x * BM;   // 8 M tiles (fast dim -> W reuse per wave)
    const int colBase = blockIdx.y * BN;   // 782 N tiles

    float acc[4][8][4];
#pragma unroll
    for (int i = 0; i < 4; i++)
#pragma unroll
        for (int j = 0; j < 8; j++)
#pragma unroll
            for (int k = 0; k < 4; k++) acc[i][j][k] = 0.0f;

    // prologue: fill pipeline (STAGES-1 = 2 groups in flight)
#pragma unroll
    for (int s = 0; s < STAGES - 1; s++) {
        load_tile(sb, s, rowBase, colBase, s, tid);
        CP_COMMIT();
    }

    // ldmatrix lane offsets (same pattern as STRB=80 config; 144 ≡ 16 mod 128
    // keeps the 8-row bank rotation conflict-free)
    const uint32_t aLaneOff = (uint32_t)((lane & 15) * STRB + (lane >> 4) * 16);
    const uint32_t bLaneOff = (uint32_t)((lane & 7) * STRB + ((lane >> 3) & 1) * 16 +
                                         (lane >> 4) * 8 * STRB);

#pragma unroll
    for (int kt = 0; kt < NT; kt++) {
        // RAW: my own cp.async group for stage kt%3 done (<=1 newer group)
        CP_WAIT(STAGES - 2);
        // WAR + cross-thread RAW: all warps past compute kt-1 (which read stage
        // (kt-1)%3 == (kt+2)%3, the one written below); waits drained first.
        __syncthreads();
        if (kt + STAGES - 1 < NT)
            load_tile(sb, (kt + STAGES - 1) % STAGES, rowBase, colBase,
                      kt + STAGES - 1, tid);
        CP_COMMIT();   // UNCONDITIONAL: empty tail groups keep wait_group's
                       // count invariant (R6 lesson).
        uint32_t st = sb + (kt % STAGES) * STG_BYTES;

#pragma unroll
        for (int ks = 0; ks < 4; ks++) {
            uint32_t kOff = ks * 32;   // 16 fp16 = 32 B
            uint32_t a[4][4], b[8][2];
#pragma unroll
            for (int nb = 0; nb < 4; nb++) {   // B first: shared across all mi
                uint32_t t[4];
                LDSM4(t, st + OFF_B +
                    (uint32_t)((warpN * 64 + nb * 16) * STRB) + kOff + bLaneOff);
                b[nb * 2][0] = t[0]; b[nb * 2][1] = t[1];
                b[nb * 2 + 1][0] = t[2]; b[nb * 2 + 1][1] = t[3];
            }
#pragma unroll
            for (int mi = 0; mi < 4; mi++)
                LDSM4(a[mi], st + OFF_A +
                    (uint32_t)((warpM * 64 + mi * 16) * STRB) + kOff + aLaneOff);
#pragma unroll
            for (int mi = 0; mi < 4; mi++)
#pragma unroll
                for (int ni = 0; ni < 8; ni++)
                    MMA16816F16(acc[mi][ni], a[mi], b[ni]);
        }
        // no trailing barrier: stage reuse distance = STAGES-1 iterations
    }

    // ---------------- epilogue ----------------
    __syncthreads();   // all MMA reads done before smem reuse for srow
    float* srow = (float*)smem;
    if (tid < BM) srow[tid] = 0.0f;
    __syncthreads();

    const int g = lane >> 2;
    const int qc = (lane & 3) * 2;
#pragma unroll
    for (int mi = 0; mi < 4; mi++) {
        float p0 = 0.0f, p1 = 0.0f;
        const int rloc = warpM * 64 + mi * 16 + g;
        const int r0 = rowBase + rloc;
#pragma unroll
        for (int ni = 0; ni < 8; ni++) {
            int col = colBase + warpN * 64 + ni * 8 + qc;
            if (col < C_) {   // col even, C_ even -> covers col+1 too
                float c0 = acc[mi][ni][0], c1 = acc[mi][ni][1];
                float c2 = acc[mi][ni][2], c3 = acc[mi][ni][3];
                // streaming scalar stores (cosOut = out+1 is only 4B-aligned)
                __stcs(&cosOut[(size_t)r0 * C_ + col],           c0);
                __stcs(&cosOut[(size_t)r0 * C_ + col + 1],       c1);
                __stcs(&cosOut[(size_t)(r0 + 8) * C_ + col],     c2);
                __stcs(&cosOut[(size_t)(r0 + 8) * C_ + col + 1], c3);
                p0 += __expf(SCALE_ * c0) + __expf(SCALE_ * c1);
                p1 += __expf(SCALE_ * c2) + __expf(SCALE_ * c3);
            }
        }
        atomicAdd(&srow[rloc], p0);
        atomicAdd(&srow[rloc + 8], p1);
    }
    __syncthreads();
    if (tid < BM)
        atomicAdd(&g_rowsum[rowBase + tid], srow[tid]);
}

// ---------------------------------------------------------------------------
// Kernel 3: per-sample CosFace loss + mean. label is int32.
// ---------------------------------------------------------------------------
__global__ void loss_kernel(const float* __restrict__ cosOut,
                            const int* __restrict__ label,
                            float* __restrict__ out) {
    __shared__ float red[B_];
    const int b = threadIdx.x;
    int lab = max(0, min(label[b], C_ - 1));
    float tgt = cosOut[(size_t)b * C_ + (size_t)lab];
    float numerator = SCALE_ * (tgt - MARGIN_);
    float excl = g_rowsum[b] - __expf(SCALE_ * tgt);
    float denom = expf(numerator) + excl;
    float loss = numerator - logf(denom);
    red[b] = loss;
    __syncthreads();
#pragma unroll
    for (int o = B_ / 2; o > 0; o >>= 1) {
        if (b < o) red[b] += red[b + o];
        __syncthreads();
    }
    if (b == 0) out[0] = -red[0] / (float)B_;
}

// ---------------------------------------------------------------------------
extern "C" void kernel_launch(void* const* d_in, const int* in_sizes, int n_in,
                              void* d_out, int out_size) {
    const float* x     = (const float*)d_in[0];
    const int*   label = (const int*)d_in[1];
    const float* w     = (const float*)d_in[2];

    float* out = (float*)d_out;
    bool has_loss = (out_size > B_ * C_);
    float* cosOut = has_loss ? (out + 1) : out;

    // 1) normalize -> fp16 (x + W, one warp per row)
    {
        const int rows = C_ + B_;
        const int blocks = (rows * 32 + 255) / 256;
        split_kernel<<<blocks, 256>>>(x, w);
    }
    // 2) fp16 HMMA GEMM + fused epilogue
    {
        static int smem_set = 0;
        if (!smem_set) {
            cudaFuncSetAttribute(gemm_mma, cudaFuncAttributeMaxDynamicSharedMemorySize,
                                 SMEM_TOTAL);
            smem_set = 1;
        }
        dim3 grid(B_ / BM, C_PAD / BN);   // (8, 782): M fast -> W tile reuse per wave
        gemm_mma<<<grid, 128, SMEM_TOTAL>>>(cosOut);
    }
    // 3) loss
    if (has_loss)
        loss_kernel<<<1, B_>>>(cosOut, label, out);
}

// round 15
// speedup vs baseline: 2.0343x; 1.0031x over previous
#include <cuda_runtime.h>
#include <cuda_fp16.h>
#include <math.h>
#include <stdint.h>

#define B_ 1024
#define D_ 512
#define C_ 100000
#define C_PAD 100096        // 782 * 128
#define SCALE_ 30.0f
#define MARGIN_ 0.4f

#define BM 128
#define BN 128
#define BK 64
#define NT (D_ / BK)        // 8 k-tiles
#define STAGES 3

#define STRB 144            // 64 fp16 = 128B data + 16B pad (conflict-free ldmatrix)
#define OFF_A 0
#define OFF_B (128 * STRB)
#define STG_BYTES (2 * 128 * STRB)      // 36864 per stage
#define SMEM_TOTAL (STAGES * STG_BYTES) // 110592

// ---------------- device scratch ----------------
__device__ __half g_Wh[(size_t)C_PAD * D_];   // normalized W, fp16 (padding rows stay 0)
__device__ __half g_Ah[B_ * D_];              // normalized x, fp16
__device__ float g_rowsum[B_];

// ---------------- helpers ----------------
__device__ __forceinline__ uint32_t smem_u32(const void* p) {
    uint32_t a;
    asm("{ .reg .u64 t; cvta.to.shared.u64 t, %1; cvt.u32.u64 %0, t; }" : "=r"(a) : "l"(p));
    return a;
}
__device__ __forceinline__ void cp16(uint32_t dst, const void* src) {
    asm volatile("cp.async.cg.shared.global [%0], [%1], 16;" :: "r"(dst), "l"(src));
}
#define CP_COMMIT() asm volatile("cp.async.commit_group;" ::: "memory")
#define CP_WAIT(n)  asm volatile("cp.async.wait_group %0;" :: "n"(n) : "memory")

#define LDSM4(r, addr) \
    asm volatile("ldmatrix.sync.aligned.m8n8.x4.shared.b16 {%0,%1,%2,%3}, [%4];" \
        : "=r"((r)[0]), "=r"((r)[1]), "=r"((r)[2]), "=r"((r)[3]) : "r"(addr))

#define MMA16816F16(c, a, b) \
    asm volatile("mma.sync.aligned.m16n8k16.row.col.f32.f16.f16.f32 " \
        "{%0,%1,%2,%3}, {%4,%5,%6,%7}, {%8,%9}, {%0,%1,%2,%3};" \
        : "+f"((c)[0]), "+f"((c)[1]), "+f"((c)[2]), "+f"((c)[3]) \
        : "r"((a)[0]), "r"((a)[1]), "r"((a)[2]), "r"((a)[3]), "r"((b)[0]), "r"((b)[1]))

// ---------------------------------------------------------------------------
// Kernel 1: fused normalize -> fp16. One warp per row. Zeroes g_rowsum.
// ---------------------------------------------------------------------------
__global__ void split_kernel(const float* __restrict__ x, const float* __restrict__ w) {
    int g = blockIdx.x * blockDim.x + threadIdx.x;
    if (g < B_) g_rowsum[g] = 0.0f;

    int row = g >> 5, lane = g & 31;
    if (row >= C_ + B_) return;

    const float* src;
    __half* dst;
    if (row < C_) {
        src = w + (size_t)row * D_;
        dst = g_Wh + (size_t)row * D_;
    } else {
        int r = row - C_;
        src = x + (size_t)r * D_;
        dst = g_Ah + (size_t)r * D_;
    }

    const float4* s4 = (const float4*)src;
    float4 v[4];
    float s = 0.0f;
#pragma unroll
    for (int i = 0; i < 4; i++) {
        v[i] = s4[lane + i * 32];
        s += v[i].x * v[i].x + v[i].y * v[i].y + v[i].z * v[i].z + v[i].w * v[i].w;
    }
#pragma unroll
    for (int o = 16; o > 0; o >>= 1) s += __shfl_xor_sync(0xffffffffu, s, o);
    float inv = 1.0f / fmaxf(sqrtf(s), 1e-12f);

#pragma unroll
    for (int i = 0; i < 4; i++) {
        int idx = (lane + i * 32) * 4;
        *(__half2*)(dst + idx)     = __floats2half2_rn(v[i].x * inv, v[i].y * inv);
        *(__half2*)(dst + idx + 2) = __floats2half2_rn(v[i].z * inv, v[i].w * inv);
    }
}

// ---------------------------------------------------------------------------
// Kernel 2: fp16 HMMA GEMM. CTA 128x128, 4 warps (2x2), warp tile 64x64,
// BK=64 (8 k-tiles), 3-stage cp.async, ONE barrier per k-tile, occupancy 2.
// Fused cosine store (streaming) + exp-rowsum epilogue.  (R14 verified best)
// ---------------------------------------------------------------------------
__device__ __forceinline__ void load_tile(uint32_t sb, int stage, int rowBase,
                                          int colBase, int kt, int tid) {
    uint32_t base = sb + stage * STG_BYTES;
    int k0 = kt * BK;
#pragma unroll
    for (int h = 0; h < 8; h++) {
        int idx = tid + h * 128;          // 0..1023
        int r = idx >> 3, seg = idx & 7;  // row 0..127, 16B segment 0..7
        uint32_t d = (uint32_t)(r * STRB + seg * 16);
        cp16(base + OFF_A + d, g_Ah + (size_t)(rowBase + r) * D_ + k0 + seg * 8);
        cp16(base + OFF_B + d, g_Wh + (size_t)(colBase + r) * D_ + k0 + seg * 8);
    }
}

__global__ __launch_bounds__(128, 2) void gemm_mma(float* __restrict__ cosOut) {
    extern __shared__ __align__(128) char smem[];
    uint32_t sb = smem_u32(smem);
    const int tid = threadIdx.x;
    const int lane = tid & 31, wid = tid >> 5;
    const int warpM = wid & 1;        // 2 warps in M (64 rows each)
    const int warpN = wid >> 1;       // 2 warps in N (64 cols each)
    const int rowBase = blockIdx.x * BM;   // 8 M tiles (fast dim -> W reuse per wave)
    const int colBase = blockIdx.y * BN;   // 782 N tiles

    float acc[4][8][4];
#pragma unroll
    for (int i = 0; i < 4; i++)
#pragma unroll
        for (int j = 0; j < 8; j++)
#pragma unroll
            for (int k = 0; k < 4; k++) acc[i][j][k] = 0.0f;

    // prologue: fill pipeline (STAGES-1 = 2 groups in flight)
#pragma unroll
    for (int s = 0; s < STAGES - 1; s++) {
        load_tile(sb, s, rowBase, colBase, s, tid);
        CP_COMMIT();
    }

    // ldmatrix lane offsets (144 ≡ 16 mod 128 keeps 8-row bank rotation clean)
    const uint32_t aLaneOff = (uint32_t)((lane & 15) * STRB + (lane >> 4) * 16);
    const uint32_t bLaneOff = (uint32_t)((lane & 7) * STRB + ((lane >> 3) & 1) * 16 +
                                         (lane >> 4) * 8 * STRB);

#pragma unroll
    for (int kt = 0; kt < NT; kt++) {
        // RAW: my own cp.async group for stage kt%3 done (<=1 newer group)
        CP_WAIT(STAGES - 2);
        // WAR + cross-thread RAW: all warps past compute kt-1 (which read stage
        // (kt+2)%3, the one written below); waits drained before barrier.
        __syncthreads();
        if (kt + STAGES - 1 < NT)
            load_tile(sb, (kt + STAGES - 1) % STAGES, rowBase, colBase,
                      kt + STAGES - 1, tid);
        CP_COMMIT();   // UNCONDITIONAL: empty tail groups keep wait_group's
                       // count invariant (R6 lesson).
        uint32_t st = sb + (kt % STAGES) * STG_BYTES;

#pragma unroll
        for (int ks = 0; ks < 4; ks++) {
            uint32_t kOff = ks * 32;   // 16 fp16 = 32 B
            uint32_t a[4][4], b[8][2];
#pragma unroll
            for (int nb = 0; nb < 4; nb++) {   // B first: shared across all mi
                uint32_t t[4];
                LDSM4(t, st + OFF_B +
                    (uint32_t)((warpN * 64 + nb * 16) * STRB) + kOff + bLaneOff);
                b[nb * 2][0] = t[0]; b[nb * 2][1] = t[1];
                b[nb * 2 + 1][0] = t[2]; b[nb * 2 + 1][1] = t[3];
            }
#pragma unroll
            for (int mi = 0; mi < 4; mi++)
                LDSM4(a[mi], st + OFF_A +
                    (uint32_t)((warpM * 64 + mi * 16) * STRB) + kOff + aLaneOff);
#pragma unroll
            for (int mi = 0; mi < 4; mi++)
#pragma unroll
                for (int ni = 0; ni < 8; ni++)
                    MMA16816F16(acc[mi][ni], a[mi], b[ni]);
        }
        // no trailing barrier: stage reuse distance = STAGES-1 iterations
    }

    // ---------------- epilogue ----------------
    __syncthreads();   // all MMA reads done before smem reuse for srow
    float* srow = (float*)smem;
    if (tid < BM) srow[tid] = 0.0f;
    __syncthreads();

    const int g = lane >> 2;
    const int qc = (lane & 3) * 2;
#pragma unroll
    for (int mi = 0; mi < 4; mi++) {
        float p0 = 0.0f, p1 = 0.0f;
        const int rloc = warpM * 64 + mi * 16 + g;
        const int r0 = rowBase + rloc;
#pragma unroll
        for (int ni = 0; ni < 8; ni++) {
            int col = colBase + warpN * 64 + ni * 8 + qc;
            if (col < C_) {   // col even, C_ even -> covers col+1 too
                float c0 = acc[mi][ni][0], c1 = acc[mi][ni][1];
                float c2 = acc[mi][ni][2], c3 = acc[mi][ni][3];
                // streaming scalar stores (cosOut = out+1 is only 4B-aligned)
                __stcs(&cosOut[(size_t)r0 * C_ + col],           c0);
                __stcs(&cosOut[(size_t)r0 * C_ + col + 1],       c1);
                __stcs(&cosOut[(size_t)(r0 + 8) * C_ + col],     c2);
                __stcs(&cosOut[(size_t)(r0 + 8) * C_ + col + 1], c3);
                p0 += __expf(SCALE_ * c0) + __expf(SCALE_ * c1);
                p1 += __expf(SCALE_ * c2) + __expf(SCALE_ * c3);
            }
        }
        atomicAdd(&srow[rloc], p0);
        atomicAdd(&srow[rloc + 8], p1);
    }
    __syncthreads();
    if (tid < BM)
        atomicAdd(&g_rowsum[rowBase + tid], srow[tid]);
}

// ---------------------------------------------------------------------------
// Kernel 3: per-sample CosFace loss + mean. label is int32.
// Warp-shuffle reduction: 32 partials -> smem -> warp 0 finishes.
// ---------------------------------------------------------------------------
__global__ void loss_kernel(const float* __restrict__ cosOut,
                            const int* __restrict__ label,
                            float* __restrict__ out) {
    __shared__ float red[32];
    const int b = threadIdx.x;
    const int lane = b & 31, warp = b >> 5;

    int lab = max(0, min(label[b], C_ - 1));
    float tgt = cosOut[(size_t)b * C_ + (size_t)lab];
    float numerator = SCALE_ * (tgt - MARGIN_);
    float excl = g_rowsum[b] - __expf(SCALE_ * tgt);
    float denom = expf(numerator) + excl;
    float loss = numerator - logf(denom);

#pragma unroll
    for (int o = 16; o > 0; o >>= 1) loss += __shfl_xor_sync(0xffffffffu, loss, o);
    if (lane == 0) red[warp] = loss;
    __syncthreads();
    if (warp == 0) {
        float s = red[lane];
#pragma unroll
        for (int o = 16; o > 0; o >>= 1) s += __shfl_xor_sync(0xffffffffu, s, o);
        if (lane == 0) out[0] = -s / (float)B_;
    }
}

// ---------------------------------------------------------------------------
extern "C" void kernel_launch(void* const* d_in, const int* in_sizes, int n_in,
                              void* d_out, int out_size) {
    const float* x     = (const float*)d_in[0];
    const int*   label = (const int*)d_in[1];
    const float* w     = (const float*)d_in[2];

    float* out = (float*)d_out;
    bool has_loss = (out_size > B_ * C_);
    float* cosOut = has_loss ? (out + 1) : out;

    // 1) normalize -> fp16 (x + W, one warp per row)
    {
        const int rows = C_ + B_;
        const int blocks = (rows * 32 + 255) / 256;
        split_kernel<<<blocks, 256>>>(x, w);
    }
    // 2) fp16 HMMA GEMM + fused epilogue
    {
        static int smem_set = 0;
        if (!smem_set) {
            cudaFuncSetAttribute(gemm_mma, cudaFuncAttributeMaxDynamicSharedMemorySize,
                                 SMEM_TOTAL);
            smem_set = 1;
        }
        dim3 grid(B_ / BM, C_PAD / BN);   // (8, 782): M fast -> W tile reuse per wave
        gemm_mma<<<grid, 128, SMEM_TOTAL>>>(cosOut);
    }
    // 3) loss
    if (has_loss)
        loss_kernel<<<1, B_>>>(cosOut, label, out);
}

// round 16
// speedup vs baseline: 2.1925x; 1.0778x over previous
#include <cuda_runtime.h>
#include <cuda_fp16.h>
#include <math.h>
#include <stdint.h>

#define B_ 1024
#define D_ 512
#define C_ 100000
#define C_PAD 100096        // 782 * 128
#define SCALE_ 30.0f
#define MARGIN_ 0.4f

#define BM 128
#define BN 128
#define BK 64
#define NT (D_ / BK)        // 8 k-tiles
#define STAGES 3

#define STRB 144            // 64 fp16 = 128B data + 16B pad (conflict-free ldmatrix)
#define OFF_A 0
#define OFF_B (128 * STRB)
#define STG_BYTES (2 * 128 * STRB)      // 36864 per stage
#define SMEM_TOTAL (STAGES * STG_BYTES) // 110592

// ---------------- device scratch ----------------
__device__ __half g_Wh[(size_t)C_PAD * D_];   // normalized W, fp16 (padding rows stay 0)
__device__ __half g_Ah[B_ * D_];              // normalized x, fp16
__device__ float g_rowsum[B_];

// ---------------- helpers ----------------
__device__ __forceinline__ uint32_t smem_u32(const void* p) {
    uint32_t a;
    asm("{ .reg .u64 t; cvta.to.shared.u64 t, %1; cvt.u32.u64 %0, t; }" : "=r"(a) : "l"(p));
    return a;
}
__device__ __forceinline__ void cp16(uint32_t dst, const void* src) {
    asm volatile("cp.async.cg.shared.global [%0], [%1], 16;" :: "r"(dst), "l"(src));
}
#define CP_COMMIT() asm volatile("cp.async.commit_group;" ::: "memory")
#define CP_WAIT(n)  asm volatile("cp.async.wait_group %0;" :: "n"(n) : "memory")

#define LDSM4(r, addr) \
    asm volatile("ldmatrix.sync.aligned.m8n8.x4.shared.b16 {%0,%1,%2,%3}, [%4];" \
        : "=r"((r)[0]), "=r"((r)[1]), "=r"((r)[2]), "=r"((r)[3]) : "r"(addr))

#define MMA16816F16(c, a, b) \
    asm volatile("mma.sync.aligned.m16n8k16.row.col.f32.f16.f16.f32 " \
        "{%0,%1,%2,%3}, {%4,%5,%6,%7}, {%8,%9}, {%0,%1,%2,%3};" \
        : "+f"((c)[0]), "+f"((c)[1]), "+f"((c)[2]), "+f"((c)[3]) \
        : "r"((a)[0]), "r"((a)[1]), "r"((a)[2]), "r"((a)[3]), "r"((b)[0]), "r"((b)[1]))

// ---------------------------------------------------------------------------
// Kernel 1: fused normalize -> fp16. One warp per row. Zeroes g_rowsum.
// ---------------------------------------------------------------------------
__global__ void split_kernel(const float* __restrict__ x, const float* __restrict__ w) {
    int g = blockIdx.x * blockDim.x + threadIdx.x;
    if (g < B_) g_rowsum[g] = 0.0f;

    int row = g >> 5, lane = g & 31;
    if (row >= C_ + B_) return;

    const float* src;
    __half* dst;
    if (row < C_) {
        src = w + (size_t)row * D_;
        dst = g_Wh + (size_t)row * D_;
    } else {
        int r = row - C_;
        src = x + (size_t)r * D_;
        dst = g_Ah + (size_t)r * D_;
    }

    const float4* s4 = (const float4*)src;
    float4 v[4];
    float s = 0.0f;
#pragma unroll
    for (int i = 0; i < 4; i++) {
        v[i] = s4[lane + i * 32];
        s += v[i].x * v[i].x + v[i].y * v[i].y + v[i].z * v[i].z + v[i].w * v[i].w;
    }
#pragma unroll
    for (int o = 16; o > 0; o >>= 1) s += __shfl_xor_sync(0xffffffffu, s, o);
    float inv = 1.0f / fmaxf(sqrtf(s), 1e-12f);

#pragma unroll
    for (int i = 0; i < 4; i++) {
        int idx = (lane + i * 32) * 4;
        *(__half2*)(dst + idx)     = __floats2half2_rn(v[i].x * inv, v[i].y * inv);
        *(__half2*)(dst + idx + 2) = __floats2half2_rn(v[i].z * inv, v[i].w * inv);
    }
}

// ---------------------------------------------------------------------------
// Kernel 2: fp16 HMMA GEMM. CTA 128x128, 4 warps (2x2), warp tile 64x64,
// BK=64 (8 k-tiles), 3-stage cp.async, ONE barrier per k-tile, occupancy 2.
// Fused cosine store (streaming) + exp-rowsum epilogue (quad-reduced).
// ---------------------------------------------------------------------------
__device__ __forceinline__ void load_tile(uint32_t sb, int stage, int rowBase,
                                          int colBase, int kt, int tid) {
    uint32_t base = sb + stage * STG_BYTES;
    int k0 = kt * BK;
#pragma unroll
    for (int h = 0; h < 8; h++) {
        int idx = tid + h * 128;          // 0..1023
        int r = idx >> 3, seg = idx & 7;  // row 0..127, 16B segment 0..7
        uint32_t d = (uint32_t)(r * STRB + seg * 16);
        cp16(base + OFF_A + d, g_Ah + (size_t)(rowBase + r) * D_ + k0 + seg * 8);
        cp16(base + OFF_B + d, g_Wh + (size_t)(colBase + r) * D_ + k0 + seg * 8);
    }
}

__global__ __launch_bounds__(128, 2) void gemm_mma(float* __restrict__ cosOut) {
    extern __shared__ __align__(128) char smem[];
    uint32_t sb = smem_u32(smem);
    const int tid = threadIdx.x;
    const int lane = tid & 31, wid = tid >> 5;
    const int warpM = wid & 1;        // 2 warps in M (64 rows each)
    const int warpN = wid >> 1;       // 2 warps in N (64 cols each)
    const int rowBase = blockIdx.x * BM;   // 8 M tiles (fast dim -> W reuse per wave)
    const int colBase = blockIdx.y * BN;   // 782 N tiles

    float acc[4][8][4];
#pragma unroll
    for (int i = 0; i < 4; i++)
#pragma unroll
        for (int j = 0; j < 8; j++)
#pragma unroll
            for (int k = 0; k < 4; k++) acc[i][j][k] = 0.0f;

    // prologue: fill pipeline (STAGES-1 = 2 groups in flight)
#pragma unroll
    for (int s = 0; s < STAGES - 1; s++) {
        load_tile(sb, s, rowBase, colBase, s, tid);
        CP_COMMIT();
    }

    // ldmatrix lane offsets (144 ≡ 16 mod 128 keeps 8-row bank rotation clean)
    const uint32_t aLaneOff = (uint32_t)((lane & 15) * STRB + (lane >> 4) * 16);
    const uint32_t bLaneOff = (uint32_t)((lane & 7) * STRB + ((lane >> 3) & 1) * 16 +
                                         (lane >> 4) * 8 * STRB);

#pragma unroll
    for (int kt = 0; kt < NT; kt++) {
        // RAW: my own cp.async group for stage kt%3 done (<=1 newer group)
        CP_WAIT(STAGES - 2);
        // WAR + cross-thread RAW: all warps past compute kt-1 (which read stage
        // (kt+2)%3, the one written below); waits drained before barrier.
        __syncthreads();
        if (kt + STAGES - 1 < NT)
            load_tile(sb, (kt + STAGES - 1) % STAGES, rowBase, colBase,
                      kt + STAGES - 1, tid);
        CP_COMMIT();   // UNCONDITIONAL: empty tail groups keep wait_group's
                       // count invariant (R6 lesson).
        uint32_t st = sb + (kt % STAGES) * STG_BYTES;

#pragma unroll
        for (int ks = 0; ks < 4; ks++) {
            uint32_t kOff = ks * 32;   // 16 fp16 = 32 B
            uint32_t a[4][4], b[8][2];
#pragma unroll
            for (int nb = 0; nb < 4; nb++) {   // B first: shared across all mi
                uint32_t t[4];
                LDSM4(t, st + OFF_B +
                    (uint32_t)((warpN * 64 + nb * 16) * STRB) + kOff + bLaneOff);
                b[nb * 2][0] = t[0]; b[nb * 2][1] = t[1];
                b[nb * 2 + 1][0] = t[2]; b[nb * 2 + 1][1] = t[3];
            }
#pragma unroll
            for (int mi = 0; mi < 4; mi++)
                LDSM4(a[mi], st + OFF_A +
                    (uint32_t)((warpM * 64 + mi * 16) * STRB) + kOff + aLaneOff);
#pragma unroll
            for (int mi = 0; mi < 4; mi++)
#pragma unroll
                for (int ni = 0; ni < 8; ni++)
                    MMA16816F16(acc[mi][ni], a[mi], b[ni]);
        }
        // no trailing barrier: stage reuse distance = STAGES-1 iterations
    }

    // ---------------- epilogue ----------------
    __syncthreads();   // all MMA reads done before smem reuse for srow
    float* srow = (float*)smem;
    if (tid < BM) srow[tid] = 0.0f;
    __syncthreads();

    const int g = lane >> 2;
    const int qc = (lane & 3) * 2;
    const bool fullTile = (colBase + BN <= C_);   // 781 of 782 tiles
#pragma unroll
    for (int mi = 0; mi < 4; mi++) {
        float p0 = 0.0f, p1 = 0.0f;
        const int rloc = warpM * 64 + mi * 16 + g;
        const int r0 = rowBase + rloc;
        if (fullTile) {
#pragma unroll
            for (int ni = 0; ni < 8; ni++) {
                int col = colBase + warpN * 64 + ni * 8 + qc;
                float c0 = acc[mi][ni][0], c1 = acc[mi][ni][1];
                float c2 = acc[mi][ni][2], c3 = acc[mi][ni][3];
                // streaming scalar stores (cosOut = out+1 is only 4B-aligned)
                __stcs(&cosOut[(size_t)r0 * C_ + col],           c0);
                __stcs(&cosOut[(size_t)r0 * C_ + col + 1],       c1);
                __stcs(&cosOut[(size_t)(r0 + 8) * C_ + col],     c2);
                __stcs(&cosOut[(size_t)(r0 + 8) * C_ + col + 1], c3);
                p0 += __expf(SCALE_ * c0) + __expf(SCALE_ * c1);
                p1 += __expf(SCALE_ * c2) + __expf(SCALE_ * c3);
            }
        } else {
#pragma unroll
            for (int ni = 0; ni < 8; ni++) {
                int col = colBase + warpN * 64 + ni * 8 + qc;
                if (col < C_) {   // col even, C_ even -> covers col+1 too
                    float c0 = acc[mi][ni][0], c1 = acc[mi][ni][1];
                    float c2 = acc[mi][ni][2], c3 = acc[mi][ni][3];
                    __stcs(&cosOut[(size_t)r0 * C_ + col],           c0);
                    __stcs(&cosOut[(size_t)r0 * C_ + col + 1],       c1);
                    __stcs(&cosOut[(size_t)(r0 + 8) * C_ + col],     c2);
                    __stcs(&cosOut[(size_t)(r0 + 8) * C_ + col + 1], c3);
                    p0 += __expf(SCALE_ * c0) + __expf(SCALE_ * c1);
                    p1 += __expf(SCALE_ * c2) + __expf(SCALE_ * c3);
                }
            }
        }
        // quad reduction: lanes {4g..4g+3} hold the same rows (rloc, rloc+8)
        p0 += __shfl_xor_sync(0xffffffffu, p0, 1);
        p0 += __shfl_xor_sync(0xffffffffu, p0, 2);
        p1 += __shfl_xor_sync(0xffffffffu, p1, 1);
        p1 += __shfl_xor_sync(0xffffffffu, p1, 2);
        if ((lane & 3) == 0) {
            atomicAdd(&srow[rloc], p0);
            atomicAdd(&srow[rloc + 8], p1);
        }
    }
    __syncthreads();
    if (tid < BM)
        atomicAdd(&g_rowsum[rowBase + tid], srow[tid]);
}

// ---------------------------------------------------------------------------
// Kernel 3: per-sample CosFace loss + mean. label is int32.
// Warp-shuffle reduction: 32 partials -> smem -> warp 0 finishes.
// ---------------------------------------------------------------------------
__global__ void loss_kernel(const float* __restrict__ cosOut,
                            const int* __restrict__ label,
                            float* __restrict__ out) {
    __shared__ float red[32];
    const int b = threadIdx.x;
    const int lane = b & 31, warp = b >> 5;

    int lab = max(0, min(label[b], C_ - 1));
    float tgt = cosOut[(size_t)b * C_ + (size_t)lab];
    float numerator = SCALE_ * (tgt - MARGIN_);
    float excl = g_rowsum[b] - __expf(SCALE_ * tgt);
    float denom = expf(numerator) + excl;
    float loss = numerator - logf(denom);

#pragma unroll
    for (int o = 16; o > 0; o >>= 1) loss += __shfl_xor_sync(0xffffffffu, loss, o);
    if (lane == 0) red[warp] = loss;
    __syncthreads();
    if (warp == 0) {
        float s = red[lane];
#pragma unroll
        for (int o = 16; o > 0; o >>= 1) s += __shfl_xor_sync(0xffffffffu, s, o);
        if (lane == 0) out[0] = -s / (float)B_;
    }
}

// ---------------------------------------------------------------------------
extern "C" void kernel_launch(void* const* d_in, const int* in_sizes, int n_in,
                              void* d_out, int out_size) {
    const float* x     = (const float*)d_in[0];
    const int*   label = (const int*)d_in[1];
    const float* w     = (const float*)d_in[2];

    float* out = (float*)d_out;
    bool has_loss = (out_size > B_ * C_);
    float* cosOut = has_loss ? (out + 1) : out;

    // 1) normalize -> fp16 (x + W, one warp per row)
    {
        const int rows = C_ + B_;
        const int blocks = (rows * 32 + 255) / 256;
        split_kernel<<<blocks, 256>>>(x, w);
    }
    // 2) fp16 HMMA GEMM + fused epilogue
    {
        static int smem_set = 0;
        if (!smem_set) {
            cudaFuncSetAttribute(gemm_mma, cudaFuncAttributeMaxDynamicSharedMemorySize,
                                 SMEM_TOTAL);
            smem_set = 1;
        }
        dim3 grid(B_ / BM, C_PAD / BN);   // (8, 782): M fast -> W tile reuse per wave
        gemm_mma<<<grid, 128, SMEM_TOTAL>>>(cosOut);
    }
    // 3) loss
    if (has_loss)
        loss_kernel<<<1, B_>>>(cosOut, label, out);
}

// round 17
// speedup vs baseline: 2.2611x; 1.0313x over previous
#include <cuda_runtime.h>
#include <cuda_fp16.h>
#include <math.h>
#include <stdint.h>

#define B_ 1024
#define D_ 512
#define C_ 100000
#define C_PAD 100096        // 782 * 128
#define SCALE_ 30.0f
#define MARGIN_ 0.4f
#define SCALE_LOG2E 43.28085122666891f   // 30 * log2(e)

#define BM 128
#define BN 128
#define BK 64
#define NT (D_ / BK)        // 8 k-tiles
#define STAGES 3

#define STRB 144            // 64 fp16 = 128B data + 16B pad (conflict-free ldmatrix)
#define OFF_A 0
#define OFF_B (128 * STRB)
#define STG_BYTES (2 * 128 * STRB)      // 36864 per stage
#define OFF_SROW (STAGES * STG_BYTES)   // dedicated row-sum region (512 B)
#define SMEM_TOTAL (OFF_SROW + BM * 4)  // 111104 (2 CTAs/SM: 222208 <= 227KB)

// ---------------- device scratch ----------------
__device__ __half g_Wh[(size_t)C_PAD * D_];   // normalized W, fp16 (padding rows stay 0)
__device__ __half g_Ah[B_ * D_];              // normalized x, fp16
__device__ float g_rowsum[B_];

// ---------------- helpers ----------------
__device__ __forceinline__ uint32_t smem_u32(const void* p) {
    uint32_t a;
    asm("{ .reg .u64 t; cvta.to.shared.u64 t, %1; cvt.u32.u64 %0, t; }" : "=r"(a) : "l"(p));
    return a;
}
__device__ __forceinline__ void cp16(uint32_t dst, const void* src) {
    asm volatile("cp.async.cg.shared.global [%0], [%1], 16;" :: "r"(dst), "l"(src));
}
#define CP_COMMIT() asm volatile("cp.async.commit_group;" ::: "memory")
#define CP_WAIT(n)  asm volatile("cp.async.wait_group %0;" :: "n"(n) : "memory")

#define LDSM4(r, addr) \
    asm volatile("ldmatrix.sync.aligned.m8n8.x4.shared.b16 {%0,%1,%2,%3}, [%4];" \
        : "=r"((r)[0]), "=r"((r)[1]), "=r"((r)[2]), "=r"((r)[3]) : "r"(addr))

#define MMA16816F16(c, a, b) \
    asm volatile("mma.sync.aligned.m16n8k16.row.col.f32.f16.f16.f32 " \
        "{%0,%1,%2,%3}, {%4,%5,%6,%7}, {%8,%9}, {%0,%1,%2,%3};" \
        : "+f"((c)[0]), "+f"((c)[1]), "+f"((c)[2]), "+f"((c)[3]) \
        : "r"((a)[0]), "r"((a)[1]), "r"((a)[2]), "r"((a)[3]), "r"((b)[0]), "r"((b)[1]))

// ---------------------------------------------------------------------------
// Kernel 1: fused normalize -> fp16. One warp per row. Zeroes g_rowsum.
// ---------------------------------------------------------------------------
__global__ void split_kernel(const float* __restrict__ x, const float* __restrict__ w) {
    int g = blockIdx.x * blockDim.x + threadIdx.x;
    if (g < B_) g_rowsum[g] = 0.0f;

    int row = g >> 5, lane = g & 31;
    if (row >= C_ + B_) return;

    const float* src;
    __half* dst;
    if (row < C_) {
        src = w + (size_t)row * D_;
        dst = g_Wh + (size_t)row * D_;
    } else {
        int r = row - C_;
        src = x + (size_t)r * D_;
        dst = g_Ah + (size_t)r * D_;
    }

    const float4* s4 = (const float4*)src;
    float4 v[4];
    float s = 0.0f;
#pragma unroll
    for (int i = 0; i < 4; i++) {
        v[i] = s4[lane + i * 32];
        s += v[i].x * v[i].x + v[i].y * v[i].y + v[i].z * v[i].z + v[i].w * v[i].w;
    }
#pragma unroll
    for (int o = 16; o > 0; o >>= 1) s += __shfl_xor_sync(0xffffffffu, s, o);
    float inv = 1.0f / fmaxf(sqrtf(s), 1e-12f);

#pragma unroll
    for (int i = 0; i < 4; i++) {
        int idx = (lane + i * 32) * 4;
        *(__half2*)(dst + idx)     = __floats2half2_rn(v[i].x * inv, v[i].y * inv);
        *(__half2*)(dst + idx + 2) = __floats2half2_rn(v[i].z * inv, v[i].w * inv);
    }
}

// ---------------------------------------------------------------------------
// Kernel 2: fp16 HMMA GEMM. CTA 128x128, 4 warps (2x2), warp tile 64x64,
// BK=64 (8 k-tiles), 3-stage cp.async, ONE barrier per k-tile, occupancy 2.
// srow lives in its own smem region (zeroed in the prologue shadow, so no
// pre-epilogue barriers). Streaming cosine stores + quad-reduced exp-rowsum.
// ---------------------------------------------------------------------------
__device__ __forceinline__ void load_tile(uint32_t sb, int stage, int rowBase,
                                          int colBase, int kt, int tid) {
    uint32_t base = sb + stage * STG_BYTES;
    int k0 = kt * BK;
#pragma unroll
    for (int h = 0; h < 8; h++) {
        int idx = tid + h * 128;          // 0..1023
        int r = idx >> 3, seg = idx & 7;  // row 0..127, 16B segment 0..7
        uint32_t d = (uint32_t)(r * STRB + seg * 16);
        cp16(base + OFF_A + d, g_Ah + (size_t)(rowBase + r) * D_ + k0 + seg * 8);
        cp16(base + OFF_B + d, g_Wh + (size_t)(colBase + r) * D_ + k0 + seg * 8);
    }
}

__global__ __launch_bounds__(128, 2) void gemm_mma(float* __restrict__ cosOut) {
    extern __shared__ __align__(128) char smem[];
    uint32_t sb = smem_u32(smem);
    const int tid = threadIdx.x;
    const int lane = tid & 31, wid = tid >> 5;
    const int warpM = wid & 1;        // 2 warps in M (64 rows each)
    const int warpN = wid >> 1;       // 2 warps in N (64 cols each)
    const int rowBase = blockIdx.x * BM;   // 8 M tiles (fast dim -> W reuse per wave)
    const int colBase = blockIdx.y * BN;   // 782 N tiles

    float* srow = (float*)(smem + OFF_SROW);
    if (tid < BM) srow[tid] = 0.0f;   // dedicated region: zeroed up front, no
                                      // extra barrier (mainloop barriers order it)

    float acc[4][8][4];
#pragma unroll
    for (int i = 0; i < 4; i++)
#pragma unroll
        for (int j = 0; j < 8; j++)
#pragma unroll
            for (int k = 0; k < 4; k++) acc[i][j][k] = 0.0f;

    // prologue: fill pipeline (STAGES-1 = 2 groups in flight)
#pragma unroll
    for (int s = 0; s < STAGES - 1; s++) {
        load_tile(sb, s, rowBase, colBase, s, tid);
        CP_COMMIT();
    }

    // ldmatrix lane offsets (144 ≡ 16 mod 128 keeps 8-row bank rotation clean)
    const uint32_t aLaneOff = (uint32_t)((lane & 15) * STRB + (lane >> 4) * 16);
    const uint32_t bLaneOff = (uint32_t)((lane & 7) * STRB + ((lane >> 3) & 1) * 16 +
                                         (lane >> 4) * 8 * STRB);

#pragma unroll
    for (int kt = 0; kt < NT; kt++) {
        // RAW: my own cp.async group for stage kt%3 done (<=1 newer group)
        CP_WAIT(STAGES - 2);
        // WAR + cross-thread RAW: all warps past compute kt-1 (which read stage
        // (kt+2)%3, the one written below); waits drained before barrier.
        __syncthreads();
        if (kt + STAGES - 1 < NT)
            load_tile(sb, (kt + STAGES - 1) % STAGES, rowBase, colBase,
                      kt + STAGES - 1, tid);
        CP_COMMIT();   // UNCONDITIONAL: empty tail groups keep wait_group's
                       // count invariant (R6 lesson).
        uint32_t st = sb + (kt % STAGES) * STG_BYTES;

#pragma unroll
        for (int ks = 0; ks < 4; ks++) {
            uint32_t kOff = ks * 32;   // 16 fp16 = 32 B
            uint32_t a[4][4], b[8][2];
#pragma unroll
            for (int nb = 0; nb < 4; nb++) {   // B first: shared across all mi
                uint32_t t[4];
                LDSM4(t, st + OFF_B +
                    (uint32_t)((warpN * 64 + nb * 16) * STRB) + kOff + bLaneOff);
                b[nb * 2][0] = t[0]; b[nb * 2][1] = t[1];
                b[nb * 2 + 1][0] = t[2]; b[nb * 2 + 1][1] = t[3];
            }
#pragma unroll
            for (int mi = 0; mi < 4; mi++)
                LDSM4(a[mi], st + OFF_A +
                    (uint32_t)((warpM * 64 + mi * 16) * STRB) + kOff + aLaneOff);
#pragma unroll
            for (int mi = 0; mi < 4; mi++)
#pragma unroll
                for (int ni = 0; ni < 8; ni++)
                    MMA16816F16(acc[mi][ni], a[mi], b[ni]);
        }
        // no trailing barrier: stage reuse distance = STAGES-1 iterations
    }

    // ---------------- epilogue (no barrier needed before it: srow is in its
    // own region, already zero; quad atomics commute) ----------------
    const int g = lane >> 2;
    const int qc = (lane & 3) * 2;
    const bool fullTile = (colBase + BN <= C_);   // 781 of 782 tiles
#pragma unroll
    for (int mi = 0; mi < 4; mi++) {
        float p0 = 0.0f, p1 = 0.0f;
        const int rloc = warpM * 64 + mi * 16 + g;
        const int r0 = rowBase + rloc;
        if (fullTile) {
#pragma unroll
            for (int ni = 0; ni < 8; ni++) {
                int col = colBase + warpN * 64 + ni * 8 + qc;
                float c0 = acc[mi][ni][0], c1 = acc[mi][ni][1];
                float c2 = acc[mi][ni][2], c3 = acc[mi][ni][3];
                // streaming scalar stores (cosOut = out+1 is only 4B-aligned)
                __stcs(&cosOut[(size_t)r0 * C_ + col],           c0);
                __stcs(&cosOut[(size_t)r0 * C_ + col + 1],       c1);
                __stcs(&cosOut[(size_t)(r0 + 8) * C_ + col],     c2);
                __stcs(&cosOut[(size_t)(r0 + 8) * C_ + col + 1], c3);
                p0 += exp2f(c0 * SCALE_LOG2E) + exp2f(c1 * SCALE_LOG2E);
                p1 += exp2f(c2 * SCALE_LOG2E) + exp2f(c3 * SCALE_LOG2E);
            }
        } else {
#pragma unroll
            for (int ni = 0; ni < 8; ni++) {
                int col = colBase + warpN * 64 + ni * 8 + qc;
                if (col < C_) {   // col even, C_ even -> covers col+1 too
                    float c0 = acc[mi][ni][0], c1 = acc[mi][ni][1];
                    float c2 = acc[mi][ni][2], c3 = acc[mi][ni][3];
                    __stcs(&cosOut[(size_t)r0 * C_ + col],           c0);
                    __stcs(&cosOut[(size_t)r0 * C_ + col + 1],       c1);
                    __stcs(&cosOut[(size_t)(r0 + 8) * C_ + col],     c2);
                    __stcs(&cosOut[(size_t)(r0 + 8) * C_ + col + 1], c3);
                    p0 += exp2f(c0 * SCALE_LOG2E) + exp2f(c1 * SCALE_LOG2E);
                    p1 += exp2f(c2 * SCALE_LOG2E) + exp2f(c3 * SCALE_LOG2E);
                }
            }
        }
        // quad reduction: lanes {4g..4g+3} hold the same rows (rloc, rloc+8)
        p0 += __shfl_xor_sync(0xffffffffu, p0, 1);
        p0 += __shfl_xor_sync(0xffffffffu, p0, 2);
        p1 += __shfl_xor_sync(0xffffffffu, p1, 1);
        p1 += __shfl_xor_sync(0xffffffffu, p1, 2);
        if ((lane & 3) == 0) {
            atomicAdd(&srow[rloc], p0);
            atomicAdd(&srow[rloc + 8], p1);
        }
    }
    __syncthreads();   // all quad atomics visible before the global flush
    if (tid < BM)
        atomicAdd(&g_rowsum[rowBase + tid], srow[tid]);
}

// ---------------------------------------------------------------------------
// Kernel 3: per-sample CosFace loss + mean. label is int32.
// ---------------------------------------------------------------------------
__global__ void loss_kernel(const float* __restrict__ cosOut,
                            const int* __restrict__ label,
                            float* __restrict__ out) {
    __shared__ float red[32];
    const int b = threadIdx.x;
    const int lane = b & 31, warp = b >> 5;

    int lab = max(0, min(label[b], C_ - 1));
    float tgt = cosOut[(size_t)b * C_ + (size_t)lab];
    float numerator = SCALE_ * (tgt - MARGIN_);
    float excl = g_rowsum[b] - exp2f(tgt * SCALE_LOG2E);
    float denom = expf(numerator) + excl;
    float loss = numerator - logf(denom);

#pragma unroll
    for (int o = 16; o > 0; o >>= 1) loss += __shfl_xor_sync(0xffffffffu, loss, o);
    if (lane == 0) red[warp] = loss;
    __syncthreads();
    if (warp == 0) {
        float s = red[lane];
#pragma unroll
        for (int o = 16; o > 0; o >>= 1) s += __shfl_xor_sync(0xffffffffu, s, o);
        if (lane == 0) out[0] = -s / (float)B_;
    }
}

// ---------------------------------------------------------------------------
extern "C" void kernel_launch(void* const* d_in, const int* in_sizes, int n_in,
                              void* d_out, int out_size) {
    const float* x     = (const float*)d_in[0];
    const int*   label = (const int*)d_in[1];
    const float* w     = (const float*)d_in[2];

    float* out = (float*)d_out;
    bool has_loss = (out_size > B_ * C_);
    float* cosOut = has_loss ? (out + 1) : out;

    // 1) normalize -> fp16 (x + W, one warp per row)
    {
        const int rows = C_ + B_;
        const int blocks = (rows * 32 + 255) / 256;
        split_kernel<<<blocks, 256>>>(x, w);
    }
    // 2) fp16 HMMA GEMM + fused epilogue
    {
        static int smem_set = 0;
        if (!smem_set) {
            cudaFuncSetAttribute(gemm_mma, cudaFuncAttributeMaxDynamicSharedMemorySize,
                                 SMEM_TOTAL);
            smem_set = 1;
        }
        dim3 grid(B_ / BM, C_PAD / BN);   // (8, 782): M fast -> W tile reuse per wave
        gemm_mma<<<grid, 128, SMEM_TOTAL>>>(cosOut);
    }
    // 3) loss
    if (has_loss)
        loss_kernel<<<1, B_>>>(cosOut, label, out);
}